// round 10
// baseline (speedup 1.0000x reference)
#include <cuda_runtime.h>

#define NROWS   512      // 16 * 32
#define NP      256      // particles per row
#define OD      10       // OBS_DIM
#define AD      4        // ACTION_DIM
#define ROW_LEN 2564
#define NBLK    1024     // (row, dir) blocks

__device__ float g_partial[NBLK];
__device__ float g_action[NROWS];
__device__ float g_a0[NROWS];
__device__ int   g_cnt;          // zero-init; last block resets it each run

typedef unsigned long long ull;

__device__ __forceinline__ ull pk2(float a, float b) {
    ull r; asm("mov.b64 %0, {%1, %2};" : "=l"(r) : "f"(a), "f"(b)); return r;
}
__device__ __forceinline__ ull fma2_(ull a, ull b, ull c) {
    ull r; asm("fma.rn.f32x2 %0, %1, %2, %3;" : "=l"(r) : "l"(a), "l"(b), "l"(c)); return r;
}
__device__ __forceinline__ unsigned umin_(unsigned a, unsigned b) { return a < b ? a : b; }

__global__ __launch_bounds__(256, 7)
void chamfer_kernel(const float* __restrict__ preds,
                    const float* __restrict__ targ,
                    float* __restrict__ out) {
    const int blk = blockIdx.x;
    const int r   = blk >> 1;        // row = b*32 + h
    const int dir = blk & 1;         // 0: candidates=obs, query=targ (idx1, w=3); 1: swapped
    const int t   = threadIdx.x;     // query column (0..255)

    __shared__ float obs_s[NP * OD];        // 10 KB
    __shared__ float obt_s[NP * OD];        // 10 KB
    __shared__ ulonglong2 sxy[NP / 2];      // packed (x-pair, y-pair)  2 KB
    __shared__ ulonglong2 szw[NP / 2];      // packed (z-pair, w-pair)  2 KB
    __shared__ float red[256];
    __shared__ int s_last;

    // ---- stage both rows (float4: base (r*2564+4)*4 is 16B-aligned) ----
    const float4* pr4 = (const float4*)(preds + (size_t)r * ROW_LEN + AD);
    const float4* tg4 = (const float4*)(targ  + (size_t)r * ROW_LEN + AD);
    #pragma unroll
    for (int i = t; i < NP * OD / 4; i += 256) {
        ((float4*)obs_s)[i] = pr4[i];
        ((float4*)obt_s)[i] = tg4[i];
    }
    __syncthreads();

    const float* scan = dir ? obt_s : obs_s;   // candidates (argmin over these)
    const float* mine = dir ? obs_s : obt_s;   // query side

    // ---- pack candidate feature pairs (dims 5..8) as f32x2 ----
    if (t < NP / 2) {
        const int k0 = 2 * t, k1 = 2 * t + 1;
        float x0 = scan[k0*OD+5], y0 = scan[k0*OD+6], z0 = scan[k0*OD+7], w0 = scan[k0*OD+8];
        float x1 = scan[k1*OD+5], y1 = scan[k1*OD+6], z1 = scan[k1*OD+7], w1 = scan[k1*OD+8];
        sxy[t] = make_ulonglong2(pk2(x0, x1), pk2(y0, y1));
        szw[t] = make_ulonglong2(pk2(z0, z1), pk2(w0, w1));
    }
    __syncthreads();

    // ---- this thread's query features ----
    const float ax = mine[t*OD+5], ay = mine[t*OD+6], az = mine[t*OD+7], aw = mine[t*OD+8];
    const ull nAx = pk2(-ax, -ax), nAy = pk2(-ay, -ay), nAz = pk2(-az, -az), nAw = pk2(-aw, -aw);
    const float Kf = 1.0f + 0.5f * (ax*ax + ay*ay + az*az + aw*aw);
    const ull K2  = pk2(Kf, Kf);
    const ull c05 = pk2(0.5f, 0.5f);

    // score = K + sum_d x_d*(0.5*x_d - q_d) = 1 + d/2  (>= 1 -> sign bit 0)
    // key = (score_bits & ~0xFF) | k  -> unsigned min = first-occurrence argmin
    unsigned bestA = 0xFFFFFFFFu;
    #pragma unroll 4
    for (int kk = 0; kk < NP / 2; ++kk) {
        const ulonglong2 xy = sxy[kk];     // LDS.128 broadcast
        const ulonglong2 zw = szw[kk];     // LDS.128 broadcast

        // p_d = 0.5*x_d - q_d (independent), s accumulates (depth-4 chain)
        const ull p0 = fma2_(xy.x, c05, nAx);
        const ull p1 = fma2_(xy.y, c05, nAy);
        const ull p2 = fma2_(zw.x, c05, nAz);
        const ull p3 = fma2_(zw.y, c05, nAw);
        ull s = fma2_(xy.x, p0, K2);
        s = fma2_(xy.y, p1, s);
        s = fma2_(zw.x, p2, s);
        s = fma2_(zw.y, p3, s);

        const unsigned k0 = 2u * kk, k1 = 2u * kk + 1u;
        bestA = umin_(bestA, ((unsigned)s         & 0xFFFFFF00u) | k0);
        bestA = umin_(bestA, ((unsigned)(s >> 32) & 0xFFFFFF00u) | k1);
    }
    const int iA = bestA & 0xFF;

    // ---- L1 gather over all 10 dims (both rows in smem, full fp32) ----
    float s1 = 0.f;
    #pragma unroll
    for (int d = 0; d < OD; ++d)
        s1 += fabsf(scan[iA * OD + d] - mine[t * OD + d]);
    const float w = dir ? 1.0f : 3.0f;   // TARGET_WEIGHT on the idx1 direction
    red[t] = w * s1;
    __syncthreads();
    #pragma unroll
    for (int off = 128; off > 0; off >>= 1) {
        if (t < off) red[t] += red[t + off];
        __syncthreads();
    }

    if (t == 0) {
        g_partial[blk] = red[0];
        if (dir == 0) {
            const float* pr = preds + (size_t)r * ROW_LEN;
            const float* tg = targ  + (size_t)r * ROW_LEN;
            float al1 = 0.f;
            #pragma unroll
            for (int d = 0; d < AD; ++d) al1 += fabsf(pr[d] - tg[d]);
            al1 *= 0.25f;
            const int h = r & 31;
            g_action[r] = (h == 1) ? al1 * 10.0f : al1;
            g_a0[r]     = (h == 1) ? al1 : 0.0f;
        }
        __threadfence();
        const int ticket = atomicAdd(&g_cnt, 1);
        s_last = (ticket == NBLK - 1) ? 1 : 0;
    }
    __syncthreads();

    // ---- fused final reduction: last block to finish does it ----
    if (s_last) {
        float c = 0.f;
        for (int i = t; i < NBLK; i += 256) c += g_partial[i];
        red[t] = c;
        __syncthreads();
        #pragma unroll
        for (int off = 128; off > 0; off >>= 1) {
            if (t < off) red[t] += red[t + off];
            __syncthreads();
        }
        const float chamfer_total = red[0];
        __syncthreads();

        float a = (t < NROWS) ? g_action[t] + g_action[t + 256] : 0.f;
        red[t] = a;
        __syncthreads();
        #pragma unroll
        for (int off = 128; off > 0; off >>= 1) {
            if (t < off) red[t] += red[t + off];
            __syncthreads();
        }
        const float action_total = red[0];
        __syncthreads();

        float z = (t < NROWS) ? g_a0[t] + g_a0[t + 256] : 0.f;
        red[t] = z;
        __syncthreads();
        #pragma unroll
        for (int off = 128; off > 0; off >>= 1) {
            if (t < off) red[t] += red[t + off];
            __syncthreads();
        }
        const float a0_total = red[0];

        if (t == 0) {
            // chamfer mean = total / (4 * 512*256*10)
            out[0] = action_total * (1.0f / NROWS) + chamfer_total * (1.0f / 5242880.0f);
            out[1] = a0_total * (1.0f / 16.0f);
            g_cnt  = 0;   // reset for next graph replay
        }
    }
}

extern "C" void kernel_launch(void* const* d_in, const int* in_sizes, int n_in,
                              void* d_out, int out_size) {
    const float* preds = (const float*)d_in[0];
    const float* targ  = (const float*)d_in[1];
    chamfer_kernel<<<NBLK, 256>>>(preds, targ, (float*)d_out);
}

// round 11
// speedup vs baseline: 1.1464x; 1.1464x over previous
#include <cuda_runtime.h>

#define NROWS   512      // 16 * 32
#define NP      256      // particles per row
#define OD      10       // OBS_DIM
#define AD      4        // ACTION_DIM
#define ROW_LEN 2564
#define NBLK    1024     // (row, dir) blocks
#define C_BIAS  32.0f

__device__ float g_partial[NBLK];
__device__ float g_action[NROWS];
__device__ float g_a0[NROWS];
__device__ int   g_cnt;          // zero-init; last block resets it each run

typedef unsigned long long ull;

__device__ __forceinline__ ull pk2(float a, float b) {
    ull r; asm("mov.b64 %0, {%1, %2};" : "=l"(r) : "f"(a), "f"(b)); return r;
}
__device__ __forceinline__ ull fma2_(ull a, ull b, ull c) {
    ull r; asm("fma.rn.f32x2 %0, %1, %2, %3;" : "=l"(r) : "l"(a), "l"(b), "l"(c)); return r;
}
__device__ __forceinline__ unsigned umin_(unsigned a, unsigned b) { return a < b ? a : b; }

__global__ __launch_bounds__(128, 8)
void chamfer_kernel(const float* __restrict__ preds,
                    const float* __restrict__ targ,
                    float* __restrict__ out) {
    const int blk = blockIdx.x;
    const int r   = blk >> 1;        // row = b*32 + h
    const int dir = blk & 1;         // 0: candidates=obs, queries=targ (idx1, w=3); 1: swapped
    const int t   = threadIdx.x;     // 0..127; this thread handles queries t and t+128

    __shared__ float obs_s[NP * OD];        // 10 KB
    __shared__ float obt_s[NP * OD];        // 10 KB
    __shared__ ulonglong2 sxy[NP / 2];      // packed (x-pair, y-pair)  2 KB
    __shared__ ulonglong2 szw[NP / 2];      // packed (z-pair, w-pair)  2 KB
    __shared__ ull        shb[NP / 2];      // packed biased half-norms 1 KB
    __shared__ float red[128];
    __shared__ int s_last;

    // ---- stage both rows (float4: base (r*2564+4)*4 is 16B-aligned) ----
    const float4* pr4 = (const float4*)(preds + (size_t)r * ROW_LEN + AD);
    const float4* tg4 = (const float4*)(targ  + (size_t)r * ROW_LEN + AD);
    #pragma unroll
    for (int i = t; i < NP * OD / 4; i += 128) {
        ((float4*)obs_s)[i] = pr4[i];
        ((float4*)obt_s)[i] = tg4[i];
    }
    __syncthreads();

    const float* scan = dir ? obt_s : obs_s;   // candidates (argmin over these)
    const float* mine = dir ? obs_s : obt_s;   // queries

    // ---- pack candidate pair t: feats (dims 5..8) + biased half-norms ----
    {
        const int k0 = 2 * t, k1 = 2 * t + 1;
        float x0 = scan[k0*OD+5], y0 = scan[k0*OD+6], z0 = scan[k0*OD+7], w0 = scan[k0*OD+8];
        float x1 = scan[k1*OD+5], y1 = scan[k1*OD+6], z1 = scan[k1*OD+7], w1 = scan[k1*OD+8];
        sxy[t] = make_ulonglong2(pk2(x0, x1), pk2(y0, y1));
        szw[t] = make_ulonglong2(pk2(z0, z1), pk2(w0, w1));
        shb[t] = pk2(C_BIAS + 0.5f * (x0*x0 + y0*y0 + z0*z0 + w0*w0),
                     C_BIAS + 0.5f * (x1*x1 + y1*y1 + z1*z1 + w1*w1));
    }
    __syncthreads();

    // ---- two queries per thread: q0 = t, q1 = t + 128 ----
    const int q0 = t, q1 = t + 128;
    const float a0x = mine[q0*OD+5], a0y = mine[q0*OD+6], a0z = mine[q0*OD+7], a0w = mine[q0*OD+8];
    const float a1x = mine[q1*OD+5], a1y = mine[q1*OD+6], a1z = mine[q1*OD+7], a1w = mine[q1*OD+8];
    const ull n0x = pk2(-a0x,-a0x), n0y = pk2(-a0y,-a0y), n0z = pk2(-a0z,-a0z), n0w = pk2(-a0w,-a0w);
    const ull n1x = pk2(-a1x,-a1x), n1y = pk2(-a1y,-a1y), n1z = pk2(-a1z,-a1z), n1w = pk2(-a1w,-a1w);

    // score = C + 0.5|c|^2 - c.q  (argmin-equiv to distance; > 0 since C > 0.5|q|^2)
    // key = (score_bits & ~0x7F) | kk ; parity (even/odd cand) tracked per accumulator.
    unsigned bL0 = 0xFFFFFFFFu, bH0 = 0xFFFFFFFFu;   // query0: even / odd candidates
    unsigned bL1 = 0xFFFFFFFFu, bH1 = 0xFFFFFFFFu;   // query1
    #pragma unroll 2
    for (int kk = 0; kk < NP / 2; ++kk) {
        const ulonglong2 xy = sxy[kk];     // LDS.128 broadcast
        const ulonglong2 zw = szw[kk];     // LDS.128 broadcast
        const ull h = shb[kk];             // LDS.64  broadcast

        ull s0 = fma2_(xy.x, n0x, h);
        s0 = fma2_(xy.y, n0y, s0);
        s0 = fma2_(zw.x, n0z, s0);
        s0 = fma2_(zw.y, n0w, s0);

        ull s1 = fma2_(xy.x, n1x, h);
        s1 = fma2_(xy.y, n1y, s1);
        s1 = fma2_(zw.x, n1z, s1);
        s1 = fma2_(zw.y, n1w, s1);

        const unsigned ku = (unsigned)kk;
        bL0 = umin_(bL0, ((unsigned)s0         & 0xFFFFFF80u) | ku);
        bH0 = umin_(bH0, ((unsigned)(s0 >> 32) & 0xFFFFFF80u) | ku);
        bL1 = umin_(bL1, ((unsigned)s1         & 0xFFFFFF80u) | ku);
        bH1 = umin_(bH1, ((unsigned)(s1 >> 32) & 0xFFFFFF80u) | ku);
    }
    // merge parities; tie-break -> smallest global index (verified both directions)
    const unsigned m0 = umin_(bL0, bH0);
    const unsigned m1 = umin_(bL1, bH1);
    const int i0 = (int)(((m0 & 0x7Fu) << 1) | (m0 == bL0 ? 0u : 1u));
    const int i1 = (int)(((m1 & 0x7Fu) << 1) | (m1 == bL1 ? 0u : 1u));

    // ---- L1 gather over all 10 dims (full fp32) ----
    float s1f = 0.f, s2f = 0.f;
    #pragma unroll
    for (int d = 0; d < OD; ++d) {
        s1f += fabsf(scan[i0 * OD + d] - mine[q0 * OD + d]);
        s2f += fabsf(scan[i1 * OD + d] - mine[q1 * OD + d]);
    }
    const float w = dir ? 1.0f : 3.0f;   // TARGET_WEIGHT on the idx1 direction
    red[t] = w * (s1f + s2f);
    __syncthreads();
    #pragma unroll
    for (int off = 64; off > 0; off >>= 1) {
        if (t < off) red[t] += red[t + off];
        __syncthreads();
    }

    if (t == 0) {
        g_partial[blk] = red[0];
        if (dir == 0) {
            const float* pr = preds + (size_t)r * ROW_LEN;
            const float* tg = targ  + (size_t)r * ROW_LEN;
            float al1 = 0.f;
            #pragma unroll
            for (int d = 0; d < AD; ++d) al1 += fabsf(pr[d] - tg[d]);
            al1 *= 0.25f;
            const int h = r & 31;
            g_action[r] = (h == 1) ? al1 * 10.0f : al1;
            g_a0[r]     = (h == 1) ? al1 : 0.0f;
        }
        __threadfence();
        const int ticket = atomicAdd(&g_cnt, 1);
        s_last = (ticket == NBLK - 1) ? 1 : 0;
    }
    __syncthreads();

    // ---- fused final reduction: last block to finish does it ----
    if (s_last) {
        float c = 0.f;
        for (int i = t; i < NBLK; i += 128) c += g_partial[i];
        red[t] = c;
        __syncthreads();
        #pragma unroll
        for (int off = 64; off > 0; off >>= 1) {
            if (t < off) red[t] += red[t + off];
            __syncthreads();
        }
        const float chamfer_total = red[0];
        __syncthreads();

        float a = 0.f;
        for (int i = t; i < NROWS; i += 128) a += g_action[i];
        red[t] = a;
        __syncthreads();
        #pragma unroll
        for (int off = 64; off > 0; off >>= 1) {
            if (t < off) red[t] += red[t + off];
            __syncthreads();
        }
        const float action_total = red[0];
        __syncthreads();

        float z = 0.f;
        for (int i = t; i < NROWS; i += 128) z += g_a0[i];
        red[t] = z;
        __syncthreads();
        #pragma unroll
        for (int off = 64; off > 0; off >>= 1) {
            if (t < off) red[t] += red[t + off];
            __syncthreads();
        }
        const float a0_total = red[0];

        if (t == 0) {
            // chamfer mean = total / (4 * 512*256*10)
            out[0] = action_total * (1.0f / NROWS) + chamfer_total * (1.0f / 5242880.0f);
            out[1] = a0_total * (1.0f / 16.0f);
            g_cnt  = 0;   // reset for next graph replay
        }
    }
}

extern "C" void kernel_launch(void* const* d_in, const int* in_sizes, int n_in,
                              void* d_out, int out_size) {
    const float* preds = (const float*)d_in[0];
    const float* targ  = (const float*)d_in[1];
    chamfer_kernel<<<NBLK, 128>>>(preds, targ, (float*)d_out);
}